// round 12
// baseline (speedup 1.0000x reference)
#include <cuda_runtime.h>
#include <cuda_fp16.h>
#include <cstdint>

#define CU_T 8192
#define CU_K 2048
#define CU_N 2048
#define CU_E 8

#define BM 128
#define BN 256
#define BK 64
#define KTILES (CU_K / BK)      // 32
#define NSTAGE 4
#define STAGE_BYTES 49152       // A(16K)+B(32K), 128B rows
#define SM_TOK 0                // 128 ints
#define SM_TILES 1024
#define SM_TOTAL (SM_TILES + NSTAGE * STAGE_BYTES)   // 197632 (193KB) -> 1 CTA/SM

// ---------------- scratch (static device globals; no allocation) ----------------
__device__ __half g_Ah[(size_t)CU_T * CU_K];
__device__ __half g_Bh[(size_t)CU_E * CU_N * CU_K];   // [e][n][k] K-major
__device__ int g_cnt[CU_E];
__device__ int g_off[CU_E];
__device__ int g_idx[CU_T];

// ---------------- PTX helpers ----------------
__device__ __forceinline__ uint32_t smem_u32(const void* p) {
    uint32_t a;
    asm("{ .reg .u64 t; cvta.to.shared.u64 t, %1; cvt.u32.u64 %0, t; }"
        : "=r"(a) : "l"(p));
    return a;
}

__device__ __forceinline__ void cp_async16(uint32_t dst, const void* src) {
    asm volatile("cp.async.cg.shared.global [%0], [%1], 16;" :: "r"(dst), "l"(src));
}
#define CP_COMMIT() asm volatile("cp.async.commit_group;" ::: "memory")
#define CP_WAIT2()  asm volatile("cp.async.wait_group 2;" ::: "memory")

__device__ __forceinline__ void ldsm4(uint32_t* r, uint32_t addr) {
    asm volatile("ldmatrix.sync.aligned.m8n8.x4.shared.b16 {%0,%1,%2,%3}, [%4];"
                 : "=r"(r[0]), "=r"(r[1]), "=r"(r[2]), "=r"(r[3]) : "r"(addr));
}

__device__ __forceinline__ void mma16816(float* d, const uint32_t* a, const uint32_t* b) {
    asm volatile(
        "mma.sync.aligned.m16n8k16.row.col.f32.f16.f16.f32 "
        "{%0,%1,%2,%3}, {%4,%5,%6,%7}, {%8,%9}, {%0,%1,%2,%3};"
        : "+f"(d[0]), "+f"(d[1]), "+f"(d[2]), "+f"(d[3])
        : "r"(a[0]), "r"(a[1]), "r"(a[2]), "r"(a[3]), "r"(b[0]), "r"(b[1]));
}

// swizzled byte offset inside a 128B-row tile (16B chunks, 8-way XOR)
__device__ __forceinline__ uint32_t swz(int row, int chunk) {
    return (uint32_t)(row * 128 + ((chunk ^ (row & 7)) << 4));
}

// ---------------- prep kernels (unchanged) ----------------
__global__ void __launch_bounds__(256) k_cvt_tok(const float* __restrict__ x) {
    size_t i = ((size_t)blockIdx.x * 256 + threadIdx.x) * 8;
    float4 a = *(const float4*)(x + i);
    float4 b = *(const float4*)(x + i + 4);
    float v[8] = {a.x, a.y, a.z, a.w, b.x, b.y, b.z, b.w};
    __align__(16) __half h[8];
#pragma unroll
    for (int j = 0; j < 8; ++j) h[j] = __float2half_rn(v[j]);
    *(uint4*)(g_Ah + i) = *(uint4*)h;
}

__global__ void __launch_bounds__(256) k_cvt_w(const float* __restrict__ w) {
    __shared__ float s[64][65];
    const int e = blockIdx.z;
    const int k0 = blockIdx.y * 64;
    const int n0 = blockIdx.x * 64;
    const int tid = threadIdx.x;
#pragma unroll
    for (int i = 0; i < 4; ++i) {
        int task = tid + i * 256;
        int kr = task >> 4;
        int nc = (task & 15) * 4;
        float4 v = *(const float4*)(w + ((size_t)e * CU_K + k0 + kr) * CU_N + n0 + nc);
        s[kr][nc + 0] = v.x; s[kr][nc + 1] = v.y;
        s[kr][nc + 2] = v.z; s[kr][nc + 3] = v.w;
    }
    __syncthreads();
#pragma unroll
    for (int i = 0; i < 2; ++i) {
        int task = tid + i * 256;
        int nr = task >> 3;
        int j = (task & 7) * 8;
        __align__(16) __half h[8];
#pragma unroll
        for (int q = 0; q < 8; ++q) h[q] = __float2half_rn(s[j + q][nr]);
        size_t dst = ((size_t)e * CU_N + n0 + nr) * CU_K + k0 + j;
        *(uint4*)(g_Bh + dst) = *(uint4*)h;
    }
}

__global__ void __launch_bounds__(1024) k_bucket(const int* __restrict__ ids) {
    __shared__ int cnt[CU_E], cur[CU_E];
    const int tid = threadIdx.x;
    if (tid < CU_E) cnt[tid] = 0;
    __syncthreads();
#pragma unroll
    for (int i = 0; i < CU_T / 1024; ++i)
        atomicAdd(&cnt[ids[tid + i * 1024]], 1);
    __syncthreads();
    if (tid == 0) {
        int s = 0;
        for (int e = 0; e < CU_E; ++e) {
            g_cnt[e] = cnt[e];
            g_off[e] = s;
            cur[e] = s;
            s += cnt[e];
        }
    }
    __syncthreads();
#pragma unroll
    for (int i = 0; i < CU_T / 1024; ++i) {
        int t = tid + i * 1024;
        int p = atomicAdd(&cur[ids[t]], 1);
        g_idx[p] = t;
    }
}

// ---------------- grouped GEMM (mma.sync fp16, 64x64 warp tile) ----------------
__device__ __forceinline__ void issue_stage(uint32_t tiles_base, int stage, int kt,
                                            const int* __restrict__ toks,
                                            size_t bbase, int tid) {
    const int k0 = kt * BK;
    const uint32_t st = tiles_base + stage * STAGE_BYTES;
    // 3072 tasks = A(128 rows x 8 chunks) + B(256 rows x 8 chunks); 12 per thread
#pragma unroll
    for (int i = 0; i < 12; ++i) {
        const int task = i * 256 + tid;
        if (task < 1024) {
            const int row = task >> 3;
            const int chunk = task & 7;
            cp_async16(st + swz(row, chunk),
                       g_Ah + (size_t)toks[row] * CU_K + k0 + chunk * 8);
        } else {
            const int t = task - 1024;
            const int row = t >> 3;
            const int chunk = t & 7;
            cp_async16(st + 16384 + swz(row, chunk),
                       g_Bh + bbase + (size_t)row * CU_K + k0 + chunk * 8);
        }
    }
}

__global__ void __launch_bounds__(256, 1) moe_gemm(float* __restrict__ out) {
    const int e = blockIdx.z;
    const int cnt = g_cnt[e];
    const int m0 = blockIdx.y * BM;
    if (m0 >= cnt) return;
    const int n0 = blockIdx.x * BN;

    extern __shared__ __align__(1024) char smem[];
    const uint32_t sb = smem_u32(smem);
    const uint32_t tiles = sb + SM_TILES;
    const int tid = threadIdx.x;
    const int wid = tid >> 5;
    const int lid = tid & 31;

    int* toks_s = (int*)(smem + SM_TOK);
    if (tid < BM) {
        int lr = m0 + tid;
        toks_s[tid] = (lr < cnt) ? g_idx[g_off[e] + lr] : 0;
    }
    __syncthreads();
    const int* toks = toks_s;
    const size_t bbase = ((size_t)e * CU_N + n0) * CU_K;

    // prologue: prefetch 3 stages
#pragma unroll
    for (int s = 0; s < 3; ++s) {
        issue_stage(tiles, s, s, toks, bbase, tid);
        CP_COMMIT();
    }

    // warp tile 64x64: 2 M-warps x 4 N-warps
    const int wm = (wid & 1) * 64;
    const int wn = (wid >> 1) * 64;
    const int q = lid >> 3;
    const int r = lid & 7;

    float acc[4][8][4];
#pragma unroll
    for (int mi = 0; mi < 4; ++mi)
#pragma unroll
        for (int ni = 0; ni < 8; ++ni)
#pragma unroll
            for (int c = 0; c < 4; ++c) acc[mi][ni][c] = 0.f;

    const int arow_base = wm + ((q & 1) << 3) + r;   // + mi*16
    const int achunk = q >> 1;                       // + ks*2
    const int brow_base = wn + ((q >> 1) << 3) + r;  // + p*16
    const int bchunk = q & 1;                        // + ks*2

    int stage = 0;
    for (int kt = 0; kt < KTILES; ++kt) {
        CP_WAIT2();
        __syncthreads();

        const uint32_t stA = tiles + stage * STAGE_BYTES;
        const uint32_t stB = stA + 16384;

        uint32_t ah[2][4][4], bh[2][4][4];
        // load ks=0 fragments first (their latency is covered by the cp.async below)
#pragma unroll
        for (int mi = 0; mi < 4; ++mi)
            ldsm4(ah[0][mi], stA + swz(arow_base + mi * 16, achunk));
#pragma unroll
        for (int p = 0; p < 4; ++p)
            ldsm4(bh[0][p], stB + swz(brow_base + p * 16, bchunk));

        if (kt + 3 < KTILES) {
            int ps = stage + 3;
            if (ps >= NSTAGE) ps -= NSTAGE;
            issue_stage(tiles, ps, kt + 3, toks, bbase, tid);
        }
        CP_COMMIT();

        // ks software pipeline: ldsm(ks+1) issued before mma(ks)
#pragma unroll
        for (int ks = 0; ks < 4; ++ks) {
            if (ks < 3) {
                const int nb = (ks + 1) & 1;
#pragma unroll
                for (int mi = 0; mi < 4; ++mi)
                    ldsm4(ah[nb][mi], stA + swz(arow_base + mi * 16, (ks + 1) * 2 + achunk));
#pragma unroll
                for (int p = 0; p < 4; ++p)
                    ldsm4(bh[nb][p], stB + swz(brow_base + p * 16, (ks + 1) * 2 + bchunk));
            }
            const int b = ks & 1;
#pragma unroll
            for (int mi = 0; mi < 4; ++mi)
#pragma unroll
                for (int ni = 0; ni < 8; ++ni)
                    mma16816(acc[mi][ni], ah[b][mi], &bh[b][ni >> 1][(ni & 1) * 2]);
        }
        if (++stage == NSTAGE) stage = 0;
    }

    // epilogue: write accumulators to gathered output rows
    const int g = lid >> 2;
    const int tq = lid & 3;
#pragma unroll
    for (int mi = 0; mi < 4; ++mi) {
        const int lr0 = wm + mi * 16 + g;
        const int lr1 = lr0 + 8;
#pragma unroll
        for (int ni = 0; ni < 8; ++ni) {
            const int col = n0 + wn + ni * 8 + tq * 2;
            if (m0 + lr0 < cnt) {
                float2 v = {acc[mi][ni][0], acc[mi][ni][1]};
                *(float2*)(out + (size_t)toks[lr0] * CU_N + col) = v;
            }
            if (m0 + lr1 < cnt) {
                float2 v = {acc[mi][ni][2], acc[mi][ni][3]};
                *(float2*)(out + (size_t)toks[lr1] * CU_N + col) = v;
            }
        }
    }
}

// ---------------- launch ----------------
extern "C" void kernel_launch(void* const* d_in, const int* in_sizes, int n_in,
                              void* d_out, int out_size) {
    const float* tokens = (const float*)d_in[0];
    const float* weight = (const float*)d_in[1];
    const int*   ids    = (const int*)d_in[2];
    float* out = (float*)d_out;

    cudaFuncSetAttribute(moe_gemm, cudaFuncAttributeMaxDynamicSharedMemorySize, SM_TOTAL);

    k_cvt_tok<<<(CU_T * CU_K) / 2048, 256>>>(tokens);
    k_cvt_w<<<dim3(CU_N / 64, CU_K / 64, CU_E), 256>>>(weight);
    k_bucket<<<1, 1024>>>(ids);
    moe_gemm<<<dim3(CU_N / BN, CU_T / BM, CU_E), 256, SM_TOTAL>>>(out);
}

// round 13
// speedup vs baseline: 1.0740x; 1.0740x over previous
#include <cuda_runtime.h>
#include <cuda_fp16.h>
#include <cstdint>

#define CU_T 8192
#define CU_K 2048
#define CU_N 2048
#define CU_E 8

#define BM 128
#define BN 128
#define BK 64
#define KTILES (CU_K / BK)      // 32
#define NSTAGE 3
#define STAGE_BYTES 32768       // Ah(16K)+Bh(16K), 128B rows
#define SM_TOK 0                // 128 ints
#define SM_TILES 1024
#define SM_TOTAL (SM_TILES + NSTAGE * STAGE_BYTES)   // 99328 (97KB) -> 2 CTAs/SM

// ---------------- scratch (static device globals; no allocation) ----------------
__device__ __half g_Ah[(size_t)CU_T * CU_K];
__device__ __half g_Bh[(size_t)CU_E * CU_N * CU_K];   // [e][n][k] K-major
__device__ int g_cnt[CU_E];
__device__ int g_off[CU_E];
__device__ int g_idx[CU_T];

// ---------------- PTX helpers ----------------
__device__ __forceinline__ uint32_t smem_u32(const void* p) {
    uint32_t a;
    asm("{ .reg .u64 t; cvta.to.shared.u64 t, %1; cvt.u32.u64 %0, t; }"
        : "=r"(a) : "l"(p));
    return a;
}

__device__ __forceinline__ void cp_async16(uint32_t dst, const void* src) {
    asm volatile("cp.async.cg.shared.global [%0], [%1], 16;" :: "r"(dst), "l"(src));
}
#define CP_COMMIT() asm volatile("cp.async.commit_group;" ::: "memory")
#define CP_WAIT1()  asm volatile("cp.async.wait_group 1;" ::: "memory")

__device__ __forceinline__ void ldsm4(uint32_t* r, uint32_t addr) {
    asm volatile("ldmatrix.sync.aligned.m8n8.x4.shared.b16 {%0,%1,%2,%3}, [%4];"
                 : "=r"(r[0]), "=r"(r[1]), "=r"(r[2]), "=r"(r[3]) : "r"(addr));
}

__device__ __forceinline__ void mma16816(float* d, const uint32_t* a, const uint32_t* b) {
    asm volatile(
        "mma.sync.aligned.m16n8k16.row.col.f32.f16.f16.f32 "
        "{%0,%1,%2,%3}, {%4,%5,%6,%7}, {%8,%9}, {%0,%1,%2,%3};"
        : "+f"(d[0]), "+f"(d[1]), "+f"(d[2]), "+f"(d[3])
        : "r"(a[0]), "r"(a[1]), "r"(a[2]), "r"(a[3]), "r"(b[0]), "r"(b[1]));
}

// swizzled byte offset inside one 128x64 f16 tile (128B rows, 16B chunks, 8-way XOR)
__device__ __forceinline__ uint32_t swz(int row, int chunk) {
    return (uint32_t)(row * 128 + ((chunk ^ (row & 7)) << 4));
}

// ---------------- prep kernels ----------------
__global__ void __launch_bounds__(256) k_cvt_tok(const float* __restrict__ x) {
    size_t i = ((size_t)blockIdx.x * 256 + threadIdx.x) * 8;
    float4 a = *(const float4*)(x + i);
    float4 b = *(const float4*)(x + i + 4);
    float v[8] = {a.x, a.y, a.z, a.w, b.x, b.y, b.z, b.w};
    __align__(16) __half h[8];
#pragma unroll
    for (int j = 0; j < 8; ++j) h[j] = __float2half_rn(v[j]);
    *(uint4*)(g_Ah + i) = *(uint4*)h;
}

__global__ void __launch_bounds__(256) k_cvt_w(const float* __restrict__ w) {
    __shared__ float s[64][65];
    const int e = blockIdx.z;
    const int k0 = blockIdx.y * 64;
    const int n0 = blockIdx.x * 64;
    const int tid = threadIdx.x;
#pragma unroll
    for (int i = 0; i < 4; ++i) {
        int task = tid + i * 256;
        int kr = task >> 4;
        int nc = (task & 15) * 4;
        float4 v = *(const float4*)(w + ((size_t)e * CU_K + k0 + kr) * CU_N + n0 + nc);
        s[kr][nc + 0] = v.x; s[kr][nc + 1] = v.y;
        s[kr][nc + 2] = v.z; s[kr][nc + 3] = v.w;
    }
    __syncthreads();
#pragma unroll
    for (int i = 0; i < 2; ++i) {
        int task = tid + i * 256;
        int nr = task >> 3;
        int j = (task & 7) * 8;
        __align__(16) __half h[8];
#pragma unroll
        for (int q = 0; q < 8; ++q) h[q] = __float2half_rn(s[j + q][nr]);
        size_t dst = ((size_t)e * CU_N + n0 + nr) * CU_K + k0 + j;
        *(uint4*)(g_Bh + dst) = *(uint4*)h;
    }
}

__global__ void __launch_bounds__(1024) k_bucket(const int* __restrict__ ids) {
    __shared__ int cnt[CU_E], cur[CU_E];
    const int tid = threadIdx.x;
    if (tid < CU_E) cnt[tid] = 0;
    __syncthreads();
#pragma unroll
    for (int i = 0; i < CU_T / 1024; ++i)
        atomicAdd(&cnt[ids[tid + i * 1024]], 1);
    __syncthreads();
    if (tid == 0) {
        int s = 0;
        for (int e = 0; e < CU_E; ++e) {
            g_cnt[e] = cnt[e];
            g_off[e] = s;
            cur[e] = s;
            s += cnt[e];
        }
    }
    __syncthreads();
#pragma unroll
    for (int i = 0; i < CU_T / 1024; ++i) {
        int t = tid + i * 1024;
        int p = atomicAdd(&cur[ids[t]], 1);
        g_idx[p] = t;
    }
}

// ---------------- grouped GEMM (mma.sync fp16, BK=64, precomputed cp addressing) ----------------
// 8 cp.async per thread: 4 A rows (r0+32i, fixed chunk) + 4 B rows (r0+32i, fixed chunk)
__device__ __forceinline__ void issue8(uint32_t dA, const uint32_t* __restrict__ offA,
                                       const __half* __restrict__ pB, int k) {
#pragma unroll
    for (int i = 0; i < 4; ++i)
        cp_async16(dA + i * 4096, g_Ah + offA[i] + k);
#pragma unroll
    for (int i = 0; i < 4; ++i)
        cp_async16(dA + 16384 + i * 4096, pB + (size_t)i * 32 * CU_K + k);
}

__global__ void __launch_bounds__(256, 2) moe_gemm(float* __restrict__ out) {
    const int e = blockIdx.z;
    const int cnt = g_cnt[e];
    const int m0 = blockIdx.y * BM;
    if (m0 >= cnt) return;
    const int n0 = blockIdx.x * BN;

    extern __shared__ __align__(1024) char smem[];
    const uint32_t sb = smem_u32(smem);
    const uint32_t tiles = sb + SM_TILES;
    const int tid = threadIdx.x;
    const int wid = tid >> 5;
    const int lid = tid & 31;

    int* toks_s = (int*)(smem + SM_TOK);
    if (tid < BM) {
        int lr = m0 + tid;
        toks_s[tid] = (lr < cnt) ? g_idx[g_off[e] + lr] : 0;
    }
    __syncthreads();
    const int* toks = toks_s;
    const size_t bbase = ((size_t)e * CU_N + n0) * CU_K;

    // loop-invariant cp.async addressing
    const int r0 = tid >> 3;                 // 0..31: base row
    const int c8 = (tid & 7) << 3;           // element offset of this thread's 16B chunk
    const uint32_t dA = tiles + (uint32_t)(r0 * 128) +
                        (uint32_t)((((tid & 7) ^ (r0 & 7)) << 4));
    uint32_t offA[4];
#pragma unroll
    for (int i = 0; i < 4; ++i)
        offA[i] = (uint32_t)toks[r0 + 32 * i] * CU_K + c8;
    const __half* pB = g_Bh + bbase + (size_t)r0 * CU_K + c8;

    // prologue: prefetch 2 stages
#pragma unroll
    for (int s = 0; s < 2; ++s) {
        issue8(dA + s * STAGE_BYTES, offA, pB, s * BK);
        CP_COMMIT();
    }

    // warp / lane decomposition: warp tile 64x32
    const int wm = (wid & 1) * 64;
    const int wn = (wid >> 1) * 32;
    const int q = lid >> 3;
    const int r = lid & 7;

    float acc[4][4][4];
#pragma unroll
    for (int mi = 0; mi < 4; ++mi)
#pragma unroll
        for (int ni = 0; ni < 4; ++ni)
#pragma unroll
            for (int c = 0; c < 4; ++c) acc[mi][ni][c] = 0.f;

    const int arow_base = wm + ((q & 1) << 3) + r;   // + mi*16
    const int achunk = q >> 1;                       // + ks*2
    const int brow_base = wn + ((q >> 1) << 3) + r;  // + p*16
    const int bchunk = q & 1;                        // + ks*2

    int stage = 0;
    for (int kt = 0; kt < KTILES; ++kt) {
        CP_WAIT1();
        __syncthreads();

        const uint32_t stA = tiles + stage * STAGE_BYTES;
        const uint32_t stB = stA + 16384;

        // ks=0 fragments first: their latency overlaps the cp.async issue below
        uint32_t ah[4][4], bh[2][4];
#pragma unroll
        for (int mi = 0; mi < 4; ++mi)
            ldsm4(ah[mi], stA + swz(arow_base + mi * 16, achunk));
#pragma unroll
        for (int p = 0; p < 2; ++p)
            ldsm4(bh[p], stB + swz(brow_base + p * 16, bchunk));

        if (kt + 2 < KTILES) {
            int ps = stage + 2;
            if (ps >= NSTAGE) ps -= NSTAGE;
            issue8(dA + ps * STAGE_BYTES, offA, pB, (kt + 2) * BK);
        }
        CP_COMMIT();

#pragma unroll
        for (int ks = 0; ks < 4; ++ks) {
            if (ks > 0) {
#pragma unroll
                for (int mi = 0; mi < 4; ++mi)
                    ldsm4(ah[mi], stA + swz(arow_base + mi * 16, ks * 2 + achunk));
#pragma unroll
                for (int p = 0; p < 2; ++p)
                    ldsm4(bh[p], stB + swz(brow_base + p * 16, ks * 2 + bchunk));
            }
#pragma unroll
            for (int mi = 0; mi < 4; ++mi)
#pragma unroll
                for (int ni = 0; ni < 4; ++ni)
                    mma16816(acc[mi][ni], ah[mi], &bh[ni >> 1][(ni & 1) * 2]);
        }
        if (++stage == NSTAGE) stage = 0;
    }

    // epilogue: write accumulators to gathered output rows
    const int g = lid >> 2;
    const int tq = lid & 3;
#pragma unroll
    for (int mi = 0; mi < 4; ++mi) {
        const int lr0 = wm + mi * 16 + g;
        const int lr1 = lr0 + 8;
#pragma unroll
        for (int ni = 0; ni < 4; ++ni) {
            const int col = n0 + wn + ni * 8 + tq * 2;
            if (m0 + lr0 < cnt) {
                float2 v = {acc[mi][ni][0], acc[mi][ni][1]};
                *(float2*)(out + (size_t)toks[lr0] * CU_N + col) = v;
            }
            if (m0 + lr1 < cnt) {
                float2 v = {acc[mi][ni][2], acc[mi][ni][3]};
                *(float2*)(out + (size_t)toks[lr1] * CU_N + col) = v;
            }
        }
    }
}

// ---------------- launch ----------------
extern "C" void kernel_launch(void* const* d_in, const int* in_sizes, int n_in,
                              void* d_out, int out_size) {
    const float* tokens = (const float*)d_in[0];
    const float* weight = (const float*)d_in[1];
    const int*   ids    = (const int*)d_in[2];
    float* out = (float*)d_out;

    cudaFuncSetAttribute(moe_gemm, cudaFuncAttributeMaxDynamicSharedMemorySize, SM_TOTAL);

    k_cvt_tok<<<(CU_T * CU_K) / 2048, 256>>>(tokens);
    k_cvt_w<<<dim3(CU_N / 64, CU_K / 64, CU_E), 256>>>(weight);
    k_bucket<<<1, 1024>>>(ids);
    moe_gemm<<<dim3(CU_N / BN, CU_T / BM, CU_E), 256, SM_TOTAL>>>(out);
}